// round 1
// baseline (speedup 1.0000x reference)
#include <cuda_runtime.h>
#include <cuda_bf16.h>
#include <math.h>

// Problem constants (shapes are fixed by the dataset)
#define NROWS 8192
#define HID   128
#define OUTC  64
#define GDIM  192          // [h(64) | x(128)]
#define RET_ELEMS (NROWS * NROWS)

// ---------------------------------------------------------------------------
// Scratch (device globals; no dynamic allocation allowed)
// ---------------------------------------------------------------------------
__device__ float g_y1[NROWS * HID];    // x @ w1
__device__ float g_z1[NROWS * HID];    // segsum(y1)
__device__ float g_h1[NROWS * OUTC];   // x @ fc_w + fc_b
__device__ float g_y2[NROWS * OUTC];   // relu(z1 + w1_b) @ w2
__device__ float g_z2[NROWS * OUTC];   // segsum(y2)
__device__ float g_G [NROWS * GDIM];   // [h | x]
__device__ float g_stats[2 * OUTC];    // colsum(h), colsumsq(h)

// ---------------------------------------------------------------------------
// Zero the accumulation buffers (must be re-zeroed every graph replay)
// ---------------------------------------------------------------------------
__global__ void zero_all() {
    int i = blockIdx.x * blockDim.x + threadIdx.x;
    if (i < NROWS * HID)  g_z1[i] = 0.f;
    if (i < NROWS * OUTC) g_z2[i] = 0.f;
    if (i < 2 * OUTC)     g_stats[i] = 0.f;
}

// ---------------------------------------------------------------------------
// Small GEMM: C[M,Nc] = transform(A[M,128]) @ B[128,Nc] (+cbias)
// transform = relu(A + abias) when relu!=0.
// BM=64, BN=64, BK=16, 256 threads, 4x4 per thread.
// ---------------------------------------------------------------------------
__global__ void __launch_bounds__(256) small_gemm(
    const float* __restrict__ A, const float* __restrict__ abias,
    const float* __restrict__ B, const float* __restrict__ cbias,
    float* __restrict__ C, int M, int Nc, int relu)
{
    __shared__ float As[16][64];
    __shared__ float Bs[16][64];

    const int row0 = blockIdx.x * 64;
    const int col0 = blockIdx.y * 64;
    const int tid = threadIdx.x;
    const int tx = tid & 15, ty = tid >> 4;

    float acc[4][4];
#pragma unroll
    for (int i = 0; i < 4; i++)
#pragma unroll
        for (int j = 0; j < 4; j++) acc[i][j] = 0.f;

    for (int k0 = 0; k0 < HID; k0 += 16) {
        // A tile: 64 rows x 16 k
        {
            int r = tid >> 2;
            int c4 = (tid & 3) * 4;
            float4 v = *(const float4*)(A + (size_t)(row0 + r) * HID + k0 + c4);
            if (relu) {
                v.x = fmaxf(v.x + abias[k0 + c4 + 0], 0.f);
                v.y = fmaxf(v.y + abias[k0 + c4 + 1], 0.f);
                v.z = fmaxf(v.z + abias[k0 + c4 + 2], 0.f);
                v.w = fmaxf(v.w + abias[k0 + c4 + 3], 0.f);
            }
            As[c4 + 0][r] = v.x; As[c4 + 1][r] = v.y;
            As[c4 + 2][r] = v.z; As[c4 + 3][r] = v.w;
        }
        // B tile: 16 k x 64 cols
        {
            int kr = tid >> 4;
            int c = (tid & 15) * 4;
            float4 v = *(const float4*)(B + (size_t)(k0 + kr) * Nc + col0 + c);
            *(float4*)&Bs[kr][c] = v;
        }
        __syncthreads();
#pragma unroll
        for (int kk = 0; kk < 16; kk++) {
            float av[4], bv[4];
#pragma unroll
            for (int i = 0; i < 4; i++) av[i] = As[kk][ty * 4 + i];
#pragma unroll
            for (int j = 0; j < 4; j++) bv[j] = Bs[kk][tx * 4 + j];
#pragma unroll
            for (int i = 0; i < 4; i++)
#pragma unroll
                for (int j = 0; j < 4; j++) acc[i][j] += av[i] * bv[j];
        }
        __syncthreads();
    }

#pragma unroll
    for (int i = 0; i < 4; i++) {
#pragma unroll
        for (int j = 0; j < 4; j++) {
            int c = col0 + tx * 4 + j;
            float cb = cbias ? cbias[c] : 0.f;
            C[(size_t)(row0 + ty * 4 + i) * Nc + c] = acc[i][j] + cb;
        }
    }
}

// ---------------------------------------------------------------------------
// Segment sum: out[dst[e]] += feat[src[e]], feature width F (div by 4).
// One warp per edge (grid-stride), float4 loads, scalar float atomics.
// ---------------------------------------------------------------------------
__global__ void segsum_kernel(const float* __restrict__ feat,
                              const int* __restrict__ src,
                              const int* __restrict__ dst,
                              float* __restrict__ out, int E, int F)
{
    int gw   = (blockIdx.x * blockDim.x + threadIdx.x) >> 5;
    int lane = threadIdx.x & 31;
    int nw   = (gridDim.x * blockDim.x) >> 5;
    int Fq   = F >> 2;
    for (int e = gw; e < E; e += nw) {
        int s = src[e];
        int d = dst[e];
        if (lane < Fq) {
            const float4 v = *(const float4*)(feat + (size_t)s * F + lane * 4);
            float* od = out + (size_t)d * F + lane * 4;
            atomicAdd(od + 0, v.x);
            atomicAdd(od + 1, v.y);
            atomicAdd(od + 2, v.z);
            atomicAdd(od + 3, v.w);
        }
    }
}

// ---------------------------------------------------------------------------
// Build h, pack G = [h | x], accumulate column stats for BN.
// blockDim = (64, 8); one row-group of 8 per block.
// ---------------------------------------------------------------------------
__global__ void build_h(const float* __restrict__ h1, const float* __restrict__ z2,
                        const float* __restrict__ w2b, const float* __restrict__ x,
                        const float* __restrict__ epsv,
                        float* __restrict__ G, float* __restrict__ stats)
{
    __shared__ float ssum[OUTC];
    __shared__ float ssq[OUTC];
    int c = threadIdx.x;          // 0..63
    int ty = threadIdx.y;         // 0..7
    if (ty == 0) { ssum[c] = 0.f; ssq[c] = 0.f; }
    __syncthreads();

    int r = blockIdx.x * 8 + ty;
    float e  = epsv[r];
    float hv = (1.f - e) * h1[(size_t)r * OUTC + c]
             + e * (z2[(size_t)r * OUTC + c] + w2b[c]);
    G[(size_t)r * GDIM + c]            = hv;
    G[(size_t)r * GDIM + OUTC + c]     = x[(size_t)r * HID + c];
    G[(size_t)r * GDIM + OUTC + 64 + c] = x[(size_t)r * HID + 64 + c];
    atomicAdd(&ssum[c], hv);
    atomicAdd(&ssq[c], hv * hv);
    __syncthreads();
    if (ty == 0) {
        atomicAdd(&stats[c], ssum[c]);
        atomicAdd(&stats[OUTC + c], ssq[c]);
    }
}

// ---------------------------------------------------------------------------
// BatchNorm output: h_bn = (h - mean) * rsqrt(var + eps) * gamma + beta
// ---------------------------------------------------------------------------
__global__ void bn_out(const float* __restrict__ G, const float* __restrict__ stats,
                       const float* __restrict__ gamma, const float* __restrict__ beta,
                       float* __restrict__ out)
{
    int i = blockIdx.x * blockDim.x + threadIdx.x;
    if (i >= NROWS * OUTC) return;
    int r = i >> 6;
    int c = i & 63;
    float inv = 1.f / (float)NROWS;
    float mean = stats[c] * inv;
    float var  = stats[OUTC + c] * inv - mean * mean;
    out[i] = (G[(size_t)r * GDIM + c] - mean) * rsqrtf(var + 1e-5f) * gamma[c] + beta[c];
}

// ---------------------------------------------------------------------------
// Big symmetric GEMM: C = 0.5 * G * G^T, G: 8192x192, C: 8192x8192.
// Only lower-triangular block pairs (bi<=bj among 64 blocks of 128) computed;
// off-diagonal tiles are mirrored. 256 threads, 8x8 per thread, BK=16,
// double-buffered smem.
// ---------------------------------------------------------------------------
__global__ void __launch_bounds__(256, 2) big_syrk(const float* __restrict__ G,
                                                   float* __restrict__ C)
{
    __shared__ float As[2][16][128];
    __shared__ float Bs[2][16][128];

    int idx = blockIdx.x;
    int bi = 0;
    while (bi < 63 && (64 * (bi + 1) - ((bi + 1) * bi) / 2) <= idx) bi++;
    int bj = bi + (idx - (64 * bi - (bi * (bi - 1)) / 2));

    const int tid = threadIdx.x;
    const int tx = tid & 15, ty = tid >> 4;
    const int lr = tid >> 1;           // 0..127 load row
    const int lc = (tid & 1) * 8;      // 0 or 8 load col offset

    const float* Ag = G + (size_t)(bi * 128 + lr) * GDIM + lc;
    const float* Bg = G + (size_t)(bj * 128 + lr) * GDIM + lc;

    float acc[8][8];
#pragma unroll
    for (int i = 0; i < 8; i++)
#pragma unroll
        for (int j = 0; j < 8; j++) acc[i][j] = 0.f;

    // prologue: chunk 0 into buffer 0
    {
        float4 a0 = *(const float4*)(Ag + 0);
        float4 a1 = *(const float4*)(Ag + 4);
        float4 b0 = *(const float4*)(Bg + 0);
        float4 b1 = *(const float4*)(Bg + 4);
        As[0][lc + 0][lr] = a0.x; As[0][lc + 1][lr] = a0.y;
        As[0][lc + 2][lr] = a0.z; As[0][lc + 3][lr] = a0.w;
        As[0][lc + 4][lr] = a1.x; As[0][lc + 5][lr] = a1.y;
        As[0][lc + 6][lr] = a1.z; As[0][lc + 7][lr] = a1.w;
        Bs[0][lc + 0][lr] = b0.x; Bs[0][lc + 1][lr] = b0.y;
        Bs[0][lc + 2][lr] = b0.z; Bs[0][lc + 3][lr] = b0.w;
        Bs[0][lc + 4][lr] = b1.x; Bs[0][lc + 5][lr] = b1.y;
        Bs[0][lc + 6][lr] = b1.z; Bs[0][lc + 7][lr] = b1.w;
    }
    __syncthreads();

#pragma unroll
    for (int t = 0; t < 12; t++) {
        const int cur = t & 1, nxt = cur ^ 1;
        float4 a0, a1, b0, b1;
        if (t < 11) {
            const float* Ap = Ag + (t + 1) * 16;
            const float* Bp = Bg + (t + 1) * 16;
            a0 = *(const float4*)(Ap + 0);
            a1 = *(const float4*)(Ap + 4);
            b0 = *(const float4*)(Bp + 0);
            b1 = *(const float4*)(Bp + 4);
        }
#pragma unroll
        for (int kk = 0; kk < 16; kk++) {
            float av[8], bv[8];
            *(float4*)&av[0] = *(const float4*)&As[cur][kk][ty * 8 + 0];
            *(float4*)&av[4] = *(const float4*)&As[cur][kk][ty * 8 + 4];
            *(float4*)&bv[0] = *(const float4*)&Bs[cur][kk][tx * 8 + 0];
            *(float4*)&bv[4] = *(const float4*)&Bs[cur][kk][tx * 8 + 4];
#pragma unroll
            for (int i = 0; i < 8; i++)
#pragma unroll
                for (int j = 0; j < 8; j++) acc[i][j] += av[i] * bv[j];
        }
        if (t < 11) {
            As[nxt][lc + 0][lr] = a0.x; As[nxt][lc + 1][lr] = a0.y;
            As[nxt][lc + 2][lr] = a0.z; As[nxt][lc + 3][lr] = a0.w;
            As[nxt][lc + 4][lr] = a1.x; As[nxt][lc + 5][lr] = a1.y;
            As[nxt][lc + 6][lr] = a1.z; As[nxt][lc + 7][lr] = a1.w;
            Bs[nxt][lc + 0][lr] = b0.x; Bs[nxt][lc + 1][lr] = b0.y;
            Bs[nxt][lc + 2][lr] = b0.z; Bs[nxt][lc + 3][lr] = b0.w;
            Bs[nxt][lc + 4][lr] = b1.x; Bs[nxt][lc + 5][lr] = b1.y;
            Bs[nxt][lc + 6][lr] = b1.z; Bs[nxt][lc + 7][lr] = b1.w;
        }
        __syncthreads();
    }

    const int r0 = bi * 128 + ty * 8;
    const int c0 = bj * 128 + tx * 8;
#pragma unroll
    for (int i = 0; i < 8; i++) {
        float4 v0 = make_float4(0.5f * acc[i][0], 0.5f * acc[i][1],
                                0.5f * acc[i][2], 0.5f * acc[i][3]);
        float4 v1 = make_float4(0.5f * acc[i][4], 0.5f * acc[i][5],
                                0.5f * acc[i][6], 0.5f * acc[i][7]);
        *(float4*)&C[(size_t)(r0 + i) * NROWS + c0 + 0] = v0;
        *(float4*)&C[(size_t)(r0 + i) * NROWS + c0 + 4] = v1;
    }
    if (bi != bj) {
#pragma unroll
        for (int j = 0; j < 8; j++) {
            float4 v0 = make_float4(0.5f * acc[0][j], 0.5f * acc[1][j],
                                    0.5f * acc[2][j], 0.5f * acc[3][j]);
            float4 v1 = make_float4(0.5f * acc[4][j], 0.5f * acc[5][j],
                                    0.5f * acc[6][j], 0.5f * acc[7][j]);
            *(float4*)&C[(size_t)(c0 + j) * NROWS + r0 + 0] = v0;
            *(float4*)&C[(size_t)(c0 + j) * NROWS + r0 + 4] = v1;
        }
    }
}

// ---------------------------------------------------------------------------
// Launch
// Inputs: 0:x 1:adj(unused) 2:src 3:dst 4:fc_w 5:fc_b 6:w1 7:w1_b 8:w2 9:w2_b
//         10:epsilon 11:gamma 12:beta
// Output: [ret (8192*8192) | h_bn (8192*64)] f32
// ---------------------------------------------------------------------------
extern "C" void kernel_launch(void* const* d_in, const int* in_sizes, int n_in,
                              void* d_out, int out_size)
{
    const float* x     = (const float*)d_in[0];
    const int*   src   = (const int*)d_in[2];
    const int*   dst   = (const int*)d_in[3];
    const float* fc_w  = (const float*)d_in[4];
    const float* fc_b  = (const float*)d_in[5];
    const float* w1    = (const float*)d_in[6];
    const float* w1_b  = (const float*)d_in[7];
    const float* w2    = (const float*)d_in[8];
    const float* w2_b  = (const float*)d_in[9];
    const float* epsv  = (const float*)d_in[10];
    const float* gamma = (const float*)d_in[11];
    const float* beta  = (const float*)d_in[12];
    const int E = in_sizes[2];

    float* out_ret = (float*)d_out;
    float* out_bn  = (float*)d_out + (size_t)RET_ELEMS;

    float *y1, *z1, *h1, *y2, *z2, *G, *stats;
    cudaGetSymbolAddress((void**)&y1, g_y1);
    cudaGetSymbolAddress((void**)&z1, g_z1);
    cudaGetSymbolAddress((void**)&h1, g_h1);
    cudaGetSymbolAddress((void**)&y2, g_y2);
    cudaGetSymbolAddress((void**)&z2, g_z2);
    cudaGetSymbolAddress((void**)&G,  g_G);
    cudaGetSymbolAddress((void**)&stats, g_stats);

    // 1. zero accumulators
    zero_all<<<(NROWS * HID + 255) / 256, 256>>>();

    // 2. y1 = x @ w1   (segsum pushed through the matmul by linearity)
    small_gemm<<<dim3(NROWS / 64, HID / 64), 256>>>(x, nullptr, w1, nullptr,
                                                    y1, NROWS, HID, 0);
    // 3. h1 = x @ fc_w + fc_b
    small_gemm<<<dim3(NROWS / 64, OUTC / 64), 256>>>(x, nullptr, fc_w, fc_b,
                                                     h1, NROWS, OUTC, 0);
    // 4. z1 = segsum(y1)
    segsum_kernel<<<2048, 256>>>(y1, src, dst, z1, E, HID);

    // 5. y2 = relu(z1 + w1_b) @ w2    (w2_b added after second segsum)
    small_gemm<<<dim3(NROWS / 64, OUTC / 64), 256>>>(z1, w1_b, w2, nullptr,
                                                     y2, NROWS, OUTC, 1);
    // 6. z2 = segsum(y2)
    segsum_kernel<<<2048, 256>>>(y2, src, dst, z2, E, OUTC);

    // 7. h = (1-eps)*h1 + eps*(z2 + w2_b); G = [h | x]; column stats
    build_h<<<NROWS / 8, dim3(64, 8)>>>(h1, z2, w2_b, x, epsv, G, stats);

    // 8. h_bn
    bn_out<<<(NROWS * OUTC + 255) / 256, 256>>>(G, stats, gamma, beta, out_bn);

    // 9. ret = 0.5 * G G^T (symmetric, triangular tiles + mirror)
    big_syrk<<<(64 * 65) / 2, 256>>>(G, out_ret);
}

// round 3
// speedup vs baseline: 1.5138x; 1.5138x over previous
#include <cuda_runtime.h>
#include <cuda_bf16.h>
#include <cstdint>
#include <math.h>

#define NROWS 8192
#define HID   128
#define OUTC  64
#define GDIM  192          // [h(64) | x(128)]
#define TK    384          // [hi(192) | lo(192)] bf16
#define RET_ELEMS (NROWS * NROWS)

// ---------------------------------------------------------------------------
// Scratch (device globals)
// ---------------------------------------------------------------------------
__device__ float g_y1[NROWS * HID];
__device__ float g_z1[NROWS * HID];
__device__ float g_h1[NROWS * OUTC];
__device__ float g_y2[NROWS * OUTC];
__device__ float g_z2[NROWS * OUTC];
__device__ float g_h [NROWS * OUTC];          // fp32 h for BN
__device__ __nv_bfloat16 g_Gb[NROWS * TK];    // [Gh | Gl] bf16 split
__device__ float g_stats[2 * OUTC];

// ---------------------------------------------------------------------------
// helpers
// ---------------------------------------------------------------------------
__device__ __forceinline__ uint32_t smem_u32(const void* p) {
    uint32_t a;
    asm("{ .reg .u64 t; cvta.to.shared.u64 t, %1; cvt.u32.u64 %0, t; }" : "=r"(a) : "l"(p));
    return a;
}
__device__ __forceinline__ void ldm_x4(uint32_t* r, uint32_t addr) {
    asm volatile("ldmatrix.sync.aligned.m8n8.x4.shared.b16 {%0,%1,%2,%3}, [%4];"
                 : "=r"(r[0]), "=r"(r[1]), "=r"(r[2]), "=r"(r[3]) : "r"(addr));
}
__device__ __forceinline__ void mma16816(float* d, const uint32_t* a, const uint32_t* b) {
    asm volatile("mma.sync.aligned.m16n8k16.row.col.f32.bf16.bf16.f32 "
                 "{%0,%1,%2,%3}, {%4,%5,%6,%7}, {%8,%9}, {%0,%1,%2,%3};"
                 : "+f"(d[0]), "+f"(d[1]), "+f"(d[2]), "+f"(d[3])
                 : "r"(a[0]), "r"(a[1]), "r"(a[2]), "r"(a[3]), "r"(b[0]), "r"(b[1]));
}

// ---------------------------------------------------------------------------
// zero accumulators
// ---------------------------------------------------------------------------
__global__ void zero_all() {
    int i = blockIdx.x * blockDim.x + threadIdx.x;
    if (i < NROWS * HID)  g_z1[i] = 0.f;
    if (i < NROWS * OUTC) g_z2[i] = 0.f;
    if (i < 2 * OUTC)     g_stats[i] = 0.f;
}

// ---------------------------------------------------------------------------
// Small GEMM (unchanged, known-good)
// ---------------------------------------------------------------------------
__global__ void __launch_bounds__(256) small_gemm(
    const float* __restrict__ A, const float* __restrict__ abias,
    const float* __restrict__ B, const float* __restrict__ cbias,
    float* __restrict__ C, int M, int Nc, int relu)
{
    __shared__ float As[16][64];
    __shared__ float Bs[16][64];
    const int row0 = blockIdx.x * 64;
    const int col0 = blockIdx.y * 64;
    const int tid = threadIdx.x;
    const int tx = tid & 15, ty = tid >> 4;

    float acc[4][4];
#pragma unroll
    for (int i = 0; i < 4; i++)
#pragma unroll
        for (int j = 0; j < 4; j++) acc[i][j] = 0.f;

    for (int k0 = 0; k0 < HID; k0 += 16) {
        {
            int r = tid >> 2;
            int c4 = (tid & 3) * 4;
            float4 v = *(const float4*)(A + (size_t)(row0 + r) * HID + k0 + c4);
            if (relu) {
                v.x = fmaxf(v.x + abias[k0 + c4 + 0], 0.f);
                v.y = fmaxf(v.y + abias[k0 + c4 + 1], 0.f);
                v.z = fmaxf(v.z + abias[k0 + c4 + 2], 0.f);
                v.w = fmaxf(v.w + abias[k0 + c4 + 3], 0.f);
            }
            As[c4 + 0][r] = v.x; As[c4 + 1][r] = v.y;
            As[c4 + 2][r] = v.z; As[c4 + 3][r] = v.w;
        }
        {
            int kr = tid >> 4;
            int c = (tid & 15) * 4;
            float4 v = *(const float4*)(B + (size_t)(k0 + kr) * Nc + col0 + c);
            *(float4*)&Bs[kr][c] = v;
        }
        __syncthreads();
#pragma unroll
        for (int kk = 0; kk < 16; kk++) {
            float av[4], bv[4];
#pragma unroll
            for (int i = 0; i < 4; i++) av[i] = As[kk][ty * 4 + i];
#pragma unroll
            for (int j = 0; j < 4; j++) bv[j] = Bs[kk][tx * 4 + j];
#pragma unroll
            for (int i = 0; i < 4; i++)
#pragma unroll
                for (int j = 0; j < 4; j++) acc[i][j] += av[i] * bv[j];
        }
        __syncthreads();
    }
#pragma unroll
    for (int i = 0; i < 4; i++)
#pragma unroll
        for (int j = 0; j < 4; j++) {
            int c = col0 + tx * 4 + j;
            float cb = cbias ? cbias[c] : 0.f;
            C[(size_t)(row0 + ty * 4 + i) * Nc + c] = acc[i][j] + cb;
        }
}

// ---------------------------------------------------------------------------
// Segment sum (unchanged)
// ---------------------------------------------------------------------------
__global__ void segsum_kernel(const float* __restrict__ feat,
                              const int* __restrict__ src,
                              const int* __restrict__ dst,
                              float* __restrict__ out, int E, int F)
{
    int gw   = (blockIdx.x * blockDim.x + threadIdx.x) >> 5;
    int lane = threadIdx.x & 31;
    int nw   = (gridDim.x * blockDim.x) >> 5;
    int Fq   = F >> 2;
    for (int e = gw; e < E; e += nw) {
        int s = src[e];
        int d = dst[e];
        if (lane < Fq) {
            const float4 v = *(const float4*)(feat + (size_t)s * F + lane * 4);
            float* od = out + (size_t)d * F + lane * 4;
            atomicAdd(od + 0, v.x);
            atomicAdd(od + 1, v.y);
            atomicAdd(od + 2, v.z);
            atomicAdd(od + 3, v.w);
        }
    }
}

// ---------------------------------------------------------------------------
// Build h, bf16 hi/lo split of G=[h|x] into g_Gb, BN stats.
// ---------------------------------------------------------------------------
__device__ __forceinline__ void split_store(__nv_bfloat16* Gb, size_t r, int col, float v) {
    __nv_bfloat16 hi = __float2bfloat16(v);
    __nv_bfloat16 lo = __float2bfloat16(v - __bfloat162float(hi));
    Gb[r * TK + col]        = hi;
    Gb[r * TK + GDIM + col] = lo;
}

__global__ void build_h(const float* __restrict__ h1, const float* __restrict__ z2,
                        const float* __restrict__ w2b, const float* __restrict__ x,
                        const float* __restrict__ epsv,
                        float* __restrict__ h_out, __nv_bfloat16* __restrict__ Gb,
                        float* __restrict__ stats)
{
    __shared__ float ssum[OUTC];
    __shared__ float ssq[OUTC];
    int c = threadIdx.x;
    int ty = threadIdx.y;
    if (ty == 0) { ssum[c] = 0.f; ssq[c] = 0.f; }
    __syncthreads();

    size_t r = blockIdx.x * 8 + ty;
    float e  = epsv[r];
    float hv = (1.f - e) * h1[r * OUTC + c] + e * (z2[r * OUTC + c] + w2b[c]);
    h_out[r * OUTC + c] = hv;
    split_store(Gb, r, c, hv);
    split_store(Gb, r, OUTC + c,      x[r * HID + c]);
    split_store(Gb, r, OUTC + 64 + c, x[r * HID + 64 + c]);
    atomicAdd(&ssum[c], hv);
    atomicAdd(&ssq[c], hv * hv);
    __syncthreads();
    if (ty == 0) {
        atomicAdd(&stats[c], ssum[c]);
        atomicAdd(&stats[OUTC + c], ssq[c]);
    }
}

__global__ void bn_out(const float* __restrict__ h, const float* __restrict__ stats,
                       const float* __restrict__ gamma, const float* __restrict__ beta,
                       float* __restrict__ out)
{
    int i = blockIdx.x * blockDim.x + threadIdx.x;
    if (i >= NROWS * OUTC) return;
    int c = i & 63;
    float inv = 1.f / (float)NROWS;
    float mean = stats[c] * inv;
    float var  = stats[OUTC + c] * inv - mean * mean;
    out[i] = (h[i] - mean) * rsqrtf(var + 1e-5f) * gamma[c] + beta[c];
}

// ---------------------------------------------------------------------------
// HMMA SYRK: C = 0.5*(Gh Gh^T + Gh Gl^T + Gl Gh^T) over 128x128 tiles.
// mma.sync m16n8k16 bf16 (sm_80+ path; tcgen05 unavailable on plain sm_103).
// 8 warps: 2x4 grid, each warp 64x32. Full K=384 tiles resident in smem,
// padded rows (392 bf16 = 784B) -> conflict-free ldmatrix.
// ---------------------------------------------------------------------------
#define RSB 392                                   // padded row stride (bf16)
#define SMEM_TILE_B (128 * RSB * 2)               // 100352 bytes per tile
#define SYRK_SMEM   (2 * SMEM_TILE_B)             // 200704 bytes

__global__ void __launch_bounds__(256, 1) big_syrk_mma(
    const __nv_bfloat16* __restrict__ Gb, float* __restrict__ C)
{
    extern __shared__ char smem[];
    char* sA = smem;
    char* sB = smem + SMEM_TILE_B;

    const int tid = threadIdx.x;
    const int wid = tid >> 5;
    const int lid = tid & 31;

    // lower-triangular tile enumeration (bi <= bj)
    int idx = blockIdx.x;
    int bi = 0;
    while (bi < 63 && (64 * (bi + 1) - ((bi + 1) * bi) / 2) <= idx) bi++;
    int bj = bi + (idx - (64 * bi - (bi * (bi - 1)) / 2));

    // ---- load A (rows bi*128..) and B (rows bj*128..) tiles, 384 bf16/row ----
    {
        const uint4* Asrc = (const uint4*)(Gb + (size_t)(bi * 128) * TK);
        const uint4* Bsrc = (const uint4*)(Gb + (size_t)(bj * 128) * TK);
#pragma unroll 4
        for (int i = tid; i < 128 * 48; i += 256) {
            int row = i / 48, q = i % 48;
            *(uint4*)(sA + row * 784 + q * 16) = Asrc[(size_t)row * 48 + q];
        }
#pragma unroll 4
        for (int i = tid; i < 128 * 48; i += 256) {
            int row = i / 48, q = i % 48;
            *(uint4*)(sB + row * 784 + q * 16) = Bsrc[(size_t)row * 48 + q];
        }
    }
    __syncthreads();

    const uint32_t smA = smem_u32(sA);
    const uint32_t smB = smem_u32(sB);

    const int wm = wid >> 2;           // 0..1 -> rows 64*wm
    const int wn = wid & 3;            // 0..3 -> cols 32*wn
    const int m_base = wm * 64;
    const int n0 = wn * 32;

    // ldmatrix lane address components
    const int aRow = m_base + (lid & 15);
    const int aColH = (lid >> 4) * 8;                    // +0 / +8 within k16
    const int bRow = n0 + ((lid >> 4) * 8) + (lid & 7);  // n rows
    const int bColH = ((lid >> 3) & 1) * 8;

    float acc[4][4][4];
#pragma unroll
    for (int mf = 0; mf < 4; mf++)
#pragma unroll
        for (int nf = 0; nf < 4; nf++)
#pragma unroll
            for (int q = 0; q < 4; q++) acc[mf][nf][q] = 0.f;

    const int kaoff[3] = {0, 0, 192};
    const int kboff[3] = {0, 192, 0};

#pragma unroll
    for (int p = 0; p < 3; p++) {
#pragma unroll
        for (int s = 0; s < 12; s++) {
            const int ka = kaoff[p] + s * 16;
            const int kb = kboff[p] + s * 16;
            uint32_t a[4][4];
#pragma unroll
            for (int mf = 0; mf < 4; mf++)
                ldm_x4(a[mf], smA + (uint32_t)((aRow + mf * 16) * 784 + (ka + aColH) * 2));
            uint32_t b[4][2];
#pragma unroll
            for (int q = 0; q < 2; q++) {
                uint32_t r[4];
                ldm_x4(r, smB + (uint32_t)((bRow + q * 16) * 784 + (kb + bColH) * 2));
                b[2 * q + 0][0] = r[0]; b[2 * q + 0][1] = r[1];
                b[2 * q + 1][0] = r[2]; b[2 * q + 1][1] = r[3];
            }
#pragma unroll
            for (int mf = 0; mf < 4; mf++)
#pragma unroll
                for (int nf = 0; nf < 4; nf++)
                    mma16816(acc[mf][nf], a[mf], b[nf]);
        }
    }

    // ---- epilogue: direct stores, then transpose-stage for mirror tile ----
    const int r0g = bi * 128, c0g = bj * 128;
    const int lrow = lid >> 2;
    const int lcol = (lid & 3) * 2;

#pragma unroll
    for (int mf = 0; mf < 4; mf++) {
#pragma unroll
        for (int nf = 0; nf < 4; nf++) {
            int row = m_base + mf * 16 + lrow;
            int col = n0 + nf * 8 + lcol;
            float2 v0 = make_float2(0.5f * acc[mf][nf][0], 0.5f * acc[mf][nf][1]);
            float2 v1 = make_float2(0.5f * acc[mf][nf][2], 0.5f * acc[mf][nf][3]);
            *(float2*)(C + (size_t)(r0g + row) * NROWS + c0g + col)     = v0;
            *(float2*)(C + (size_t)(r0g + row + 8) * NROWS + c0g + col) = v1;
        }
    }

    if (bi != bj) {
        __syncthreads();                       // smem tiles no longer needed
        float* smT = (float*)smem;             // [128 cols][132]
#pragma unroll
        for (int mf = 0; mf < 4; mf++) {
#pragma unroll
            for (int nf = 0; nf < 4; nf++) {
                int row = m_base + mf * 16 + lrow;
                int col = n0 + nf * 8 + lcol;
                smT[(col + 0) * 132 + row]     = 0.5f * acc[mf][nf][0];
                smT[(col + 1) * 132 + row]     = 0.5f * acc[mf][nf][1];
                smT[(col + 0) * 132 + row + 8] = 0.5f * acc[mf][nf][2];
                smT[(col + 1) * 132 + row + 8] = 0.5f * acc[mf][nf][3];
            }
        }
        __syncthreads();
        for (int i = tid; i < 128 * 32; i += 256) {
            int c = i >> 5, q = i & 31;
            float4 v = *(float4*)&smT[c * 132 + q * 4];
            *(float4*)(C + (size_t)(c0g + c) * NROWS + r0g + q * 4) = v;
        }
    }
}

// ---------------------------------------------------------------------------
// Launch
// Inputs: 0:x 1:adj 2:src 3:dst 4:fc_w 5:fc_b 6:w1 7:w1_b 8:w2 9:w2_b
//         10:epsilon 11:gamma 12:beta
// ---------------------------------------------------------------------------
extern "C" void kernel_launch(void* const* d_in, const int* in_sizes, int n_in,
                              void* d_out, int out_size)
{
    const float* x     = (const float*)d_in[0];
    const int*   src   = (const int*)d_in[2];
    const int*   dst   = (const int*)d_in[3];
    const float* fc_w  = (const float*)d_in[4];
    const float* fc_b  = (const float*)d_in[5];
    const float* w1    = (const float*)d_in[6];
    const float* w1_b  = (const float*)d_in[7];
    const float* w2    = (const float*)d_in[8];
    const float* w2_b  = (const float*)d_in[9];
    const float* epsv  = (const float*)d_in[10];
    const float* gamma = (const float*)d_in[11];
    const float* beta  = (const float*)d_in[12];
    const int E = in_sizes[2];

    float* out_ret = (float*)d_out;
    float* out_bn  = (float*)d_out + (size_t)RET_ELEMS;

    float *y1, *z1, *h1, *y2, *z2, *h, *stats;
    __nv_bfloat16* Gb;
    cudaGetSymbolAddress((void**)&y1, g_y1);
    cudaGetSymbolAddress((void**)&z1, g_z1);
    cudaGetSymbolAddress((void**)&h1, g_h1);
    cudaGetSymbolAddress((void**)&y2, g_y2);
    cudaGetSymbolAddress((void**)&z2, g_z2);
    cudaGetSymbolAddress((void**)&h,  g_h);
    cudaGetSymbolAddress((void**)&Gb, g_Gb);
    cudaGetSymbolAddress((void**)&stats, g_stats);

    cudaFuncSetAttribute(big_syrk_mma, cudaFuncAttributeMaxDynamicSharedMemorySize,
                         SYRK_SMEM);

    zero_all<<<(NROWS * HID + 255) / 256, 256>>>();

    small_gemm<<<dim3(NROWS / 64, HID / 64), 256>>>(x, nullptr, w1, nullptr,
                                                    y1, NROWS, HID, 0);
    small_gemm<<<dim3(NROWS / 64, OUTC / 64), 256>>>(x, nullptr, fc_w, fc_b,
                                                     h1, NROWS, OUTC, 0);
    segsum_kernel<<<2048, 256>>>(y1, src, dst, z1, E, HID);

    small_gemm<<<dim3(NROWS / 64, OUTC / 64), 256>>>(z1, w1_b, w2, nullptr,
                                                     y2, NROWS, OUTC, 1);
    segsum_kernel<<<2048, 256>>>(y2, src, dst, z2, E, OUTC);

    build_h<<<NROWS / 8, dim3(64, 8)>>>(h1, z2, w2_b, x, epsv, h, Gb, stats);
    bn_out<<<(NROWS * OUTC + 255) / 256, 256>>>(h, stats, gamma, beta, out_bn);

    big_syrk_mma<<<(64 * 65) / 2, 256, SYRK_SMEM>>>(Gb, out_ret);
}

// round 4
// speedup vs baseline: 1.9351x; 1.2783x over previous
#include <cuda_runtime.h>
#include <cuda_bf16.h>
#include <cstdint>
#include <math.h>

#define NROWS 8192
#define HID   128
#define OUTC  64
#define GDIM  192          // [h(64) | x(128)]
#define TK    384          // [hi(192) | lo(192)] bf16
#define EMAX  262144
#define RET_ELEMS (NROWS * NROWS)

// ---------------------------------------------------------------------------
// Scratch (device globals)
// ---------------------------------------------------------------------------
__device__ float g_y1[NROWS * HID];
__device__ float g_z1[NROWS * HID];
__device__ float g_h1[NROWS * OUTC];
__device__ float g_y2[NROWS * OUTC];
__device__ float g_z2[NROWS * OUTC];
__device__ float g_h [NROWS * OUTC];          // fp32 h for BN
__device__ __nv_bfloat16 g_Gb[NROWS * TK];    // [Gh | Gl] bf16 split
__device__ float g_stats[2 * OUTC];
// CSR scratch
__device__ int g_deg[NROWS];
__device__ int g_off[NROWS + 1];
__device__ int g_cur[NROWS];
__device__ int g_csr[EMAX];

// ---------------------------------------------------------------------------
// helpers
// ---------------------------------------------------------------------------
__device__ __forceinline__ uint32_t smem_u32(const void* p) {
    uint32_t a;
    asm("{ .reg .u64 t; cvta.to.shared.u64 t, %1; cvt.u32.u64 %0, t; }" : "=r"(a) : "l"(p));
    return a;
}
__device__ __forceinline__ void ldm_x4(uint32_t* r, uint32_t addr) {
    asm volatile("ldmatrix.sync.aligned.m8n8.x4.shared.b16 {%0,%1,%2,%3}, [%4];"
                 : "=r"(r[0]), "=r"(r[1]), "=r"(r[2]), "=r"(r[3]) : "r"(addr));
}
__device__ __forceinline__ void mma16816(float* d, const uint32_t* a, const uint32_t* b) {
    asm volatile("mma.sync.aligned.m16n8k16.row.col.f32.bf16.bf16.f32 "
                 "{%0,%1,%2,%3}, {%4,%5,%6,%7}, {%8,%9}, {%0,%1,%2,%3};"
                 : "+f"(d[0]), "+f"(d[1]), "+f"(d[2]), "+f"(d[3])
                 : "r"(a[0]), "r"(a[1]), "r"(a[2]), "r"(a[3]), "r"(b[0]), "r"(b[1]));
}

// ---------------------------------------------------------------------------
// CSR build: zero -> histogram -> scan -> scatter
// ---------------------------------------------------------------------------
__global__ void zero_small() {
    int i = blockIdx.x * blockDim.x + threadIdx.x;
    if (i < NROWS) g_deg[i] = 0;
    if (i < 2 * OUTC) g_stats[i] = 0.f;
}

__global__ void hist_kernel(const int* __restrict__ dst, int E) {
    int i = blockIdx.x * blockDim.x + threadIdx.x;
    int stride = gridDim.x * blockDim.x;
    for (int e = i; e < E; e += stride) atomicAdd(&g_deg[dst[e]], 1);
}

__global__ void __launch_bounds__(1024) scan_kernel() {
    __shared__ int ssum[1024];
    int t = threadIdx.x;
    int v[8];
    int tot = 0;
#pragma unroll
    for (int j = 0; j < 8; j++) { v[j] = g_deg[t * 8 + j]; tot += v[j]; }
    ssum[t] = tot;
    __syncthreads();
    // Hillis-Steele inclusive scan
    for (int d = 1; d < 1024; d <<= 1) {
        int x = (t >= d) ? ssum[t - d] : 0;
        __syncthreads();
        ssum[t] += x;
        __syncthreads();
    }
    int run = ssum[t] - tot;   // exclusive prefix
#pragma unroll
    for (int j = 0; j < 8; j++) {
        g_off[t * 8 + j] = run;
        g_cur[t * 8 + j] = run;
        run += v[j];
    }
    if (t == 1023) g_off[NROWS] = run;
}

__global__ void scatter_kernel(const int* __restrict__ src,
                               const int* __restrict__ dst, int E) {
    int i = blockIdx.x * blockDim.x + threadIdx.x;
    int stride = gridDim.x * blockDim.x;
    for (int e = i; e < E; e += stride) {
        int p = atomicAdd(&g_cur[dst[e]], 1);
        g_csr[p] = src[e];
    }
}

// ---------------------------------------------------------------------------
// CSR gather segment-sum: out[d] = sum_{e in bucket(d)} feat[csr[e]]
// TPD threads per destination row, float4 per thread (F = TPD*4).
// ---------------------------------------------------------------------------
template <int TPD>
__global__ void __launch_bounds__(256) gather_kernel(
    const float* __restrict__ feat, float* __restrict__ out)
{
    const int F = TPD * 4;
    int g = (blockIdx.x * blockDim.x + threadIdx.x) / TPD;
    int lane = threadIdx.x % TPD;
    if (g >= NROWS) return;
    int b = g_off[g];
    int e = g_off[g + 1];
    float4 acc = make_float4(0.f, 0.f, 0.f, 0.f);
    float4 acc2 = make_float4(0.f, 0.f, 0.f, 0.f);
    int i = b;
    for (; i + 1 < e; i += 2) {
        int s0 = g_csr[i];
        int s1 = g_csr[i + 1];
        float4 v0 = *(const float4*)(feat + (size_t)s0 * F + lane * 4);
        float4 v1 = *(const float4*)(feat + (size_t)s1 * F + lane * 4);
        acc.x += v0.x; acc.y += v0.y; acc.z += v0.z; acc.w += v0.w;
        acc2.x += v1.x; acc2.y += v1.y; acc2.z += v1.z; acc2.w += v1.w;
    }
    if (i < e) {
        int s0 = g_csr[i];
        float4 v0 = *(const float4*)(feat + (size_t)s0 * F + lane * 4);
        acc.x += v0.x; acc.y += v0.y; acc.z += v0.z; acc.w += v0.w;
    }
    acc.x += acc2.x; acc.y += acc2.y; acc.z += acc2.z; acc.w += acc2.w;
    *(float4*)(out + (size_t)g * F + lane * 4) = acc;
}

// ---------------------------------------------------------------------------
// Small GEMM (unchanged, known-good)
// ---------------------------------------------------------------------------
__global__ void __launch_bounds__(256) small_gemm(
    const float* __restrict__ A, const float* __restrict__ abias,
    const float* __restrict__ B, const float* __restrict__ cbias,
    float* __restrict__ C, int M, int Nc, int relu)
{
    __shared__ float As[16][64];
    __shared__ float Bs[16][64];
    const int row0 = blockIdx.x * 64;
    const int col0 = blockIdx.y * 64;
    const int tid = threadIdx.x;
    const int tx = tid & 15, ty = tid >> 4;

    float acc[4][4];
#pragma unroll
    for (int i = 0; i < 4; i++)
#pragma unroll
        for (int j = 0; j < 4; j++) acc[i][j] = 0.f;

    for (int k0 = 0; k0 < HID; k0 += 16) {
        {
            int r = tid >> 2;
            int c4 = (tid & 3) * 4;
            float4 v = *(const float4*)(A + (size_t)(row0 + r) * HID + k0 + c4);
            if (relu) {
                v.x = fmaxf(v.x + abias[k0 + c4 + 0], 0.f);
                v.y = fmaxf(v.y + abias[k0 + c4 + 1], 0.f);
                v.z = fmaxf(v.z + abias[k0 + c4 + 2], 0.f);
                v.w = fmaxf(v.w + abias[k0 + c4 + 3], 0.f);
            }
            As[c4 + 0][r] = v.x; As[c4 + 1][r] = v.y;
            As[c4 + 2][r] = v.z; As[c4 + 3][r] = v.w;
        }
        {
            int kr = tid >> 4;
            int c = (tid & 15) * 4;
            float4 v = *(const float4*)(B + (size_t)(k0 + kr) * Nc + col0 + c);
            *(float4*)&Bs[kr][c] = v;
        }
        __syncthreads();
#pragma unroll
        for (int kk = 0; kk < 16; kk++) {
            float av[4], bv[4];
#pragma unroll
            for (int i = 0; i < 4; i++) av[i] = As[kk][ty * 4 + i];
#pragma unroll
            for (int j = 0; j < 4; j++) bv[j] = Bs[kk][tx * 4 + j];
#pragma unroll
            for (int i = 0; i < 4; i++)
#pragma unroll
                for (int j = 0; j < 4; j++) acc[i][j] += av[i] * bv[j];
        }
        __syncthreads();
    }
#pragma unroll
    for (int i = 0; i < 4; i++)
#pragma unroll
        for (int j = 0; j < 4; j++) {
            int c = col0 + tx * 4 + j;
            float cb = cbias ? cbias[c] : 0.f;
            C[(size_t)(row0 + ty * 4 + i) * Nc + c] = acc[i][j] + cb;
        }
}

// ---------------------------------------------------------------------------
// Build h, bf16 hi/lo split of G=[h|x] into g_Gb, BN stats.
// ---------------------------------------------------------------------------
__device__ __forceinline__ void split_store(__nv_bfloat16* Gb, size_t r, int col, float v) {
    __nv_bfloat16 hi = __float2bfloat16(v);
    __nv_bfloat16 lo = __float2bfloat16(v - __bfloat162float(hi));
    Gb[r * TK + col]        = hi;
    Gb[r * TK + GDIM + col] = lo;
}

__global__ void build_h(const float* __restrict__ h1, const float* __restrict__ z2,
                        const float* __restrict__ w2b, const float* __restrict__ x,
                        const float* __restrict__ epsv,
                        float* __restrict__ h_out, __nv_bfloat16* __restrict__ Gb,
                        float* __restrict__ stats)
{
    __shared__ float ssum[OUTC];
    __shared__ float ssq[OUTC];
    int c = threadIdx.x;
    int ty = threadIdx.y;
    if (ty == 0) { ssum[c] = 0.f; ssq[c] = 0.f; }
    __syncthreads();

    size_t r = blockIdx.x * 8 + ty;
    float e  = epsv[r];
    float hv = (1.f - e) * h1[r * OUTC + c] + e * (z2[r * OUTC + c] + w2b[c]);
    h_out[r * OUTC + c] = hv;
    split_store(Gb, r, c, hv);
    split_store(Gb, r, OUTC + c,      x[r * HID + c]);
    split_store(Gb, r, OUTC + 64 + c, x[r * HID + 64 + c]);
    atomicAdd(&ssum[c], hv);
    atomicAdd(&ssq[c], hv * hv);
    __syncthreads();
    if (ty == 0) {
        atomicAdd(&stats[c], ssum[c]);
        atomicAdd(&stats[OUTC + c], ssq[c]);
    }
}

__global__ void bn_out(const float* __restrict__ h, const float* __restrict__ stats,
                       const float* __restrict__ gamma, const float* __restrict__ beta,
                       float* __restrict__ out)
{
    int i = blockIdx.x * blockDim.x + threadIdx.x;
    if (i >= NROWS * OUTC) return;
    int c = i & 63;
    float inv = 1.f / (float)NROWS;
    float mean = stats[c] * inv;
    float var  = stats[OUTC + c] * inv - mean * mean;
    out[i] = (h[i] - mean) * rsqrtf(var + 1e-5f) * gamma[c] + beta[c];
}

// ---------------------------------------------------------------------------
// HMMA SYRK (unchanged from round 3, known-good)
// ---------------------------------------------------------------------------
#define RSB 392                                   // padded row stride (bf16)
#define SMEM_TILE_B (128 * RSB * 2)               // 100352 bytes per tile
#define SYRK_SMEM   (2 * SMEM_TILE_B)             // 200704 bytes

__global__ void __launch_bounds__(256, 1) big_syrk_mma(
    const __nv_bfloat16* __restrict__ Gb, float* __restrict__ C)
{
    extern __shared__ char smem[];
    char* sA = smem;
    char* sB = smem + SMEM_TILE_B;

    const int tid = threadIdx.x;
    const int wid = tid >> 5;
    const int lid = tid & 31;

    int idx = blockIdx.x;
    int bi = 0;
    while (bi < 63 && (64 * (bi + 1) - ((bi + 1) * bi) / 2) <= idx) bi++;
    int bj = bi + (idx - (64 * bi - (bi * (bi - 1)) / 2));

    {
        const uint4* Asrc = (const uint4*)(Gb + (size_t)(bi * 128) * TK);
        const uint4* Bsrc = (const uint4*)(Gb + (size_t)(bj * 128) * TK);
#pragma unroll 4
        for (int i = tid; i < 128 * 48; i += 256) {
            int row = i / 48, q = i % 48;
            *(uint4*)(sA + row * 784 + q * 16) = Asrc[(size_t)row * 48 + q];
        }
#pragma unroll 4
        for (int i = tid; i < 128 * 48; i += 256) {
            int row = i / 48, q = i % 48;
            *(uint4*)(sB + row * 784 + q * 16) = Bsrc[(size_t)row * 48 + q];
        }
    }
    __syncthreads();

    const uint32_t smA = smem_u32(sA);
    const uint32_t smB = smem_u32(sB);

    const int wm = wid >> 2;
    const int wn = wid & 3;
    const int m_base = wm * 64;
    const int n0 = wn * 32;

    const int aRow = m_base + (lid & 15);
    const int aColH = (lid >> 4) * 8;
    const int bRow = n0 + ((lid >> 4) * 8) + (lid & 7);
    const int bColH = ((lid >> 3) & 1) * 8;

    float acc[4][4][4];
#pragma unroll
    for (int mf = 0; mf < 4; mf++)
#pragma unroll
        for (int nf = 0; nf < 4; nf++)
#pragma unroll
            for (int q = 0; q < 4; q++) acc[mf][nf][q] = 0.f;

    const int kaoff[3] = {0, 0, 192};
    const int kboff[3] = {0, 192, 0};

#pragma unroll
    for (int p = 0; p < 3; p++) {
#pragma unroll
        for (int s = 0; s < 12; s++) {
            const int ka = kaoff[p] + s * 16;
            const int kb = kboff[p] + s * 16;
            uint32_t a[4][4];
#pragma unroll
            for (int mf = 0; mf < 4; mf++)
                ldm_x4(a[mf], smA + (uint32_t)((aRow + mf * 16) * 784 + (ka + aColH) * 2));
            uint32_t b[4][2];
#pragma unroll
            for (int q = 0; q < 2; q++) {
                uint32_t r[4];
                ldm_x4(r, smB + (uint32_t)((bRow + q * 16) * 784 + (kb + bColH) * 2));
                b[2 * q + 0][0] = r[0]; b[2 * q + 0][1] = r[1];
                b[2 * q + 1][0] = r[2]; b[2 * q + 1][1] = r[3];
            }
#pragma unroll
            for (int mf = 0; mf < 4; mf++)
#pragma unroll
                for (int nf = 0; nf < 4; nf++)
                    mma16816(acc[mf][nf], a[mf], b[nf]);
        }
    }

    const int r0g = bi * 128, c0g = bj * 128;
    const int lrow = lid >> 2;
    const int lcol = (lid & 3) * 2;

#pragma unroll
    for (int mf = 0; mf < 4; mf++) {
#pragma unroll
        for (int nf = 0; nf < 4; nf++) {
            int row = m_base + mf * 16 + lrow;
            int col = n0 + nf * 8 + lcol;
            float2 v0 = make_float2(0.5f * acc[mf][nf][0], 0.5f * acc[mf][nf][1]);
            float2 v1 = make_float2(0.5f * acc[mf][nf][2], 0.5f * acc[mf][nf][3]);
            *(float2*)(C + (size_t)(r0g + row) * NROWS + c0g + col)     = v0;
            *(float2*)(C + (size_t)(r0g + row + 8) * NROWS + c0g + col) = v1;
        }
    }

    if (bi != bj) {
        __syncthreads();
        float* smT = (float*)smem;
#pragma unroll
        for (int mf = 0; mf < 4; mf++) {
#pragma unroll
            for (int nf = 0; nf < 4; nf++) {
                int row = m_base + mf * 16 + lrow;
                int col = n0 + nf * 8 + lcol;
                smT[(col + 0) * 132 + row]     = 0.5f * acc[mf][nf][0];
                smT[(col + 1) * 132 + row]     = 0.5f * acc[mf][nf][1];
                smT[(col + 0) * 132 + row + 8] = 0.5f * acc[mf][nf][2];
                smT[(col + 1) * 132 + row + 8] = 0.5f * acc[mf][nf][3];
            }
        }
        __syncthreads();
        for (int i = tid; i < 128 * 32; i += 256) {
            int c = i >> 5, q = i & 31;
            float4 v = *(float4*)&smT[c * 132 + q * 4];
            *(float4*)(C + (size_t)(c0g + c) * NROWS + r0g + q * 4) = v;
        }
    }
}

// ---------------------------------------------------------------------------
// Launch
// Inputs: 0:x 1:adj 2:src 3:dst 4:fc_w 5:fc_b 6:w1 7:w1_b 8:w2 9:w2_b
//         10:epsilon 11:gamma 12:beta
// ---------------------------------------------------------------------------
extern "C" void kernel_launch(void* const* d_in, const int* in_sizes, int n_in,
                              void* d_out, int out_size)
{
    const float* x     = (const float*)d_in[0];
    const int*   src   = (const int*)d_in[2];
    const int*   dst   = (const int*)d_in[3];
    const float* fc_w  = (const float*)d_in[4];
    const float* fc_b  = (const float*)d_in[5];
    const float* w1    = (const float*)d_in[6];
    const float* w1_b  = (const float*)d_in[7];
    const float* w2    = (const float*)d_in[8];
    const float* w2_b  = (const float*)d_in[9];
    const float* epsv  = (const float*)d_in[10];
    const float* gamma = (const float*)d_in[11];
    const float* beta  = (const float*)d_in[12];
    const int E = in_sizes[2];

    float* out_ret = (float*)d_out;
    float* out_bn  = (float*)d_out + (size_t)RET_ELEMS;

    float *y1, *z1, *h1, *y2, *z2, *h, *stats;
    __nv_bfloat16* Gb;
    cudaGetSymbolAddress((void**)&y1, g_y1);
    cudaGetSymbolAddress((void**)&z1, g_z1);
    cudaGetSymbolAddress((void**)&h1, g_h1);
    cudaGetSymbolAddress((void**)&y2, g_y2);
    cudaGetSymbolAddress((void**)&z2, g_z2);
    cudaGetSymbolAddress((void**)&h,  g_h);
    cudaGetSymbolAddress((void**)&Gb, g_Gb);
    cudaGetSymbolAddress((void**)&stats, g_stats);

    cudaFuncSetAttribute(big_syrk_mma, cudaFuncAttributeMaxDynamicSharedMemorySize,
                         SYRK_SMEM);

    // CSR build (independent of GEMMs; deterministic structure per replay)
    zero_small<<<(NROWS + 255) / 256, 256>>>();
    hist_kernel<<<512, 256>>>(dst, E);
    scan_kernel<<<1, 1024>>>();
    scatter_kernel<<<512, 256>>>(src, dst, E);

    // y1 = x @ w1 ; h1 = x @ fc_w + fc_b
    small_gemm<<<dim3(NROWS / 64, HID / 64), 256>>>(x, nullptr, w1, nullptr,
                                                    y1, NROWS, HID, 0);
    small_gemm<<<dim3(NROWS / 64, OUTC / 64), 256>>>(x, nullptr, fc_w, fc_b,
                                                     h1, NROWS, OUTC, 0);

    // z1 = segsum(y1)  (CSR gather, 32 threads/row)
    gather_kernel<32><<<NROWS * 32 / 256, 256>>>(y1, z1);

    // y2 = relu(z1 + w1_b) @ w2
    small_gemm<<<dim3(NROWS / 64, OUTC / 64), 256>>>(z1, w1_b, w2, nullptr,
                                                     y2, NROWS, OUTC, 1);
    // z2 = segsum(y2)  (CSR gather, 16 threads/row)
    gather_kernel<16><<<NROWS * 16 / 256, 256>>>(y2, z2);

    build_h<<<NROWS / 8, dim3(64, 8)>>>(h1, z2, w2_b, x, epsv, h, Gb, stats);
    bn_out<<<(NROWS * OUTC + 255) / 256, 256>>>(h, stats, gamma, beta, out_bn);

    big_syrk_mma<<<(64 * 65) / 2, 256, SYRK_SMEM>>>(Gb, out_ret);
}

// round 5
// speedup vs baseline: 2.0958x; 1.0831x over previous
#include <cuda_runtime.h>
#include <cuda_bf16.h>
#include <cstdint>
#include <math.h>

#define NROWS 8192
#define HID   128
#define OUTC  64
#define GDIM  192          // [h(64) | x(128)]
#define TK    384          // [hi(192) | lo(192)] bf16
#define EMAX  262144
#define RET_ELEMS (NROWS * NROWS)

// ---------------------------------------------------------------------------
// Scratch (device globals)
// ---------------------------------------------------------------------------
__device__ float g_y1[NROWS * HID];
__device__ float g_z1[NROWS * HID];
__device__ float g_h1[NROWS * OUTC];
__device__ float g_y2[NROWS * OUTC];
__device__ float g_z2[NROWS * OUTC];
__device__ float g_h [NROWS * OUTC];          // fp32 h for BN
__device__ __nv_bfloat16 g_Gb[NROWS * TK];    // [Gh | Gl] bf16 split
__device__ float g_stats[2 * OUTC];
// CSR scratch
__device__ int g_deg[NROWS];
__device__ int g_off[NROWS + 1];
__device__ int g_cur[NROWS];
__device__ int g_csr[EMAX];

// ---------------------------------------------------------------------------
// helpers
// ---------------------------------------------------------------------------
__device__ __forceinline__ uint32_t smem_u32(const void* p) {
    uint32_t a;
    asm("{ .reg .u64 t; cvta.to.shared.u64 t, %1; cvt.u32.u64 %0, t; }" : "=r"(a) : "l"(p));
    return a;
}
__device__ __forceinline__ void ldm_x4(uint32_t* r, uint32_t addr) {
    asm volatile("ldmatrix.sync.aligned.m8n8.x4.shared.b16 {%0,%1,%2,%3}, [%4];"
                 : "=r"(r[0]), "=r"(r[1]), "=r"(r[2]), "=r"(r[3]) : "r"(addr));
}
__device__ __forceinline__ void mma16816(float* d, const uint32_t* a, const uint32_t* b) {
    asm volatile("mma.sync.aligned.m16n8k16.row.col.f32.bf16.bf16.f32 "
                 "{%0,%1,%2,%3}, {%4,%5,%6,%7}, {%8,%9}, {%0,%1,%2,%3};"
                 : "+f"(d[0]), "+f"(d[1]), "+f"(d[2]), "+f"(d[3])
                 : "r"(a[0]), "r"(a[1]), "r"(a[2]), "r"(a[3]), "r"(b[0]), "r"(b[1]));
}
__device__ __forceinline__ void cp16(uint32_t smem_dst, const void* gsrc) {
    asm volatile("cp.async.cg.shared.global [%0], [%1], 16;"
                 :: "r"(smem_dst), "l"(gsrc) : "memory");
}
__device__ __forceinline__ void cp_commit() {
    asm volatile("cp.async.commit_group;" ::: "memory");
}
template <int N>
__device__ __forceinline__ void cp_wait() {
    asm volatile("cp.async.wait_group %0;" :: "n"(N) : "memory");
}

// ---------------------------------------------------------------------------
// CSR build: zero -> histogram -> scan -> scatter
// ---------------------------------------------------------------------------
__global__ void zero_small() {
    int i = blockIdx.x * blockDim.x + threadIdx.x;
    if (i < NROWS) g_deg[i] = 0;
    if (i < 2 * OUTC) g_stats[i] = 0.f;
}

__global__ void hist_kernel(const int* __restrict__ dst, int E) {
    int i = blockIdx.x * blockDim.x + threadIdx.x;
    int stride = gridDim.x * blockDim.x;
    for (int e = i; e < E; e += stride) atomicAdd(&g_deg[dst[e]], 1);
}

__global__ void __launch_bounds__(1024) scan_kernel() {
    __shared__ int ssum[1024];
    int t = threadIdx.x;
    int v[8];
    int tot = 0;
#pragma unroll
    for (int j = 0; j < 8; j++) { v[j] = g_deg[t * 8 + j]; tot += v[j]; }
    ssum[t] = tot;
    __syncthreads();
    for (int d = 1; d < 1024; d <<= 1) {
        int x = (t >= d) ? ssum[t - d] : 0;
        __syncthreads();
        ssum[t] += x;
        __syncthreads();
    }
    int run = ssum[t] - tot;   // exclusive prefix
#pragma unroll
    for (int j = 0; j < 8; j++) {
        g_off[t * 8 + j] = run;
        g_cur[t * 8 + j] = run;
        run += v[j];
    }
    if (t == 1023) g_off[NROWS] = run;
}

__global__ void scatter_kernel(const int* __restrict__ src,
                               const int* __restrict__ dst, int E) {
    int i = blockIdx.x * blockDim.x + threadIdx.x;
    int stride = gridDim.x * blockDim.x;
    for (int e = i; e < E; e += stride) {
        int p = atomicAdd(&g_cur[dst[e]], 1);
        g_csr[p] = src[e];
    }
}

// ---------------------------------------------------------------------------
// CSR gather segment-sum
// ---------------------------------------------------------------------------
template <int TPD>
__global__ void __launch_bounds__(256) gather_kernel(
    const float* __restrict__ feat, float* __restrict__ out)
{
    const int F = TPD * 4;
    int g = (blockIdx.x * blockDim.x + threadIdx.x) / TPD;
    int lane = threadIdx.x % TPD;
    if (g >= NROWS) return;
    int b = g_off[g];
    int e = g_off[g + 1];
    float4 acc = make_float4(0.f, 0.f, 0.f, 0.f);
    float4 acc2 = make_float4(0.f, 0.f, 0.f, 0.f);
    int i = b;
    for (; i + 1 < e; i += 2) {
        int s0 = g_csr[i];
        int s1 = g_csr[i + 1];
        float4 v0 = *(const float4*)(feat + (size_t)s0 * F + lane * 4);
        float4 v1 = *(const float4*)(feat + (size_t)s1 * F + lane * 4);
        acc.x += v0.x; acc.y += v0.y; acc.z += v0.z; acc.w += v0.w;
        acc2.x += v1.x; acc2.y += v1.y; acc2.z += v1.z; acc2.w += v1.w;
    }
    if (i < e) {
        int s0 = g_csr[i];
        float4 v0 = *(const float4*)(feat + (size_t)s0 * F + lane * 4);
        acc.x += v0.x; acc.y += v0.y; acc.z += v0.z; acc.w += v0.w;
    }
    acc.x += acc2.x; acc.y += acc2.y; acc.z += acc2.z; acc.w += acc2.w;
    *(float4*)(out + (size_t)g * F + lane * 4) = acc;
}

// ---------------------------------------------------------------------------
// Small GEMM (unchanged, known-good)
// ---------------------------------------------------------------------------
__global__ void __launch_bounds__(256) small_gemm(
    const float* __restrict__ A, const float* __restrict__ abias,
    const float* __restrict__ B, const float* __restrict__ cbias,
    float* __restrict__ C, int M, int Nc, int relu)
{
    __shared__ float As[16][64];
    __shared__ float Bs[16][64];
    const int row0 = blockIdx.x * 64;
    const int col0 = blockIdx.y * 64;
    const int tid = threadIdx.x;
    const int tx = tid & 15, ty = tid >> 4;

    float acc[4][4];
#pragma unroll
    for (int i = 0; i < 4; i++)
#pragma unroll
        for (int j = 0; j < 4; j++) acc[i][j] = 0.f;

    for (int k0 = 0; k0 < HID; k0 += 16) {
        {
            int r = tid >> 2;
            int c4 = (tid & 3) * 4;
            float4 v = *(const float4*)(A + (size_t)(row0 + r) * HID + k0 + c4);
            if (relu) {
                v.x = fmaxf(v.x + abias[k0 + c4 + 0], 0.f);
                v.y = fmaxf(v.y + abias[k0 + c4 + 1], 0.f);
                v.z = fmaxf(v.z + abias[k0 + c4 + 2], 0.f);
                v.w = fmaxf(v.w + abias[k0 + c4 + 3], 0.f);
            }
            As[c4 + 0][r] = v.x; As[c4 + 1][r] = v.y;
            As[c4 + 2][r] = v.z; As[c4 + 3][r] = v.w;
        }
        {
            int kr = tid >> 4;
            int c = (tid & 15) * 4;
            float4 v = *(const float4*)(B + (size_t)(k0 + kr) * Nc + col0 + c);
            *(float4*)&Bs[kr][c] = v;
        }
        __syncthreads();
#pragma unroll
        for (int kk = 0; kk < 16; kk++) {
            float av[4], bv[4];
#pragma unroll
            for (int i = 0; i < 4; i++) av[i] = As[kk][ty * 4 + i];
#pragma unroll
            for (int j = 0; j < 4; j++) bv[j] = Bs[kk][tx * 4 + j];
#pragma unroll
            for (int i = 0; i < 4; i++)
#pragma unroll
                for (int j = 0; j < 4; j++) acc[i][j] += av[i] * bv[j];
        }
        __syncthreads();
    }
#pragma unroll
    for (int i = 0; i < 4; i++)
#pragma unroll
        for (int j = 0; j < 4; j++) {
            int c = col0 + tx * 4 + j;
            float cb = cbias ? cbias[c] : 0.f;
            C[(size_t)(row0 + ty * 4 + i) * Nc + c] = acc[i][j] + cb;
        }
}

// ---------------------------------------------------------------------------
// Build h, bf16 hi/lo split of G=[h|x] into g_Gb, BN stats.
// ---------------------------------------------------------------------------
__device__ __forceinline__ void split_store(__nv_bfloat16* Gb, size_t r, int col, float v) {
    __nv_bfloat16 hi = __float2bfloat16(v);
    __nv_bfloat16 lo = __float2bfloat16(v - __bfloat162float(hi));
    Gb[r * TK + col]        = hi;
    Gb[r * TK + GDIM + col] = lo;
}

__global__ void build_h(const float* __restrict__ h1, const float* __restrict__ z2,
                        const float* __restrict__ w2b, const float* __restrict__ x,
                        const float* __restrict__ epsv,
                        float* __restrict__ h_out, __nv_bfloat16* __restrict__ Gb,
                        float* __restrict__ stats)
{
    __shared__ float ssum[OUTC];
    __shared__ float ssq[OUTC];
    int c = threadIdx.x;
    int ty = threadIdx.y;
    if (ty == 0) { ssum[c] = 0.f; ssq[c] = 0.f; }
    __syncthreads();

    size_t r = blockIdx.x * 8 + ty;
    float e  = epsv[r];
    float hv = (1.f - e) * h1[r * OUTC + c] + e * (z2[r * OUTC + c] + w2b[c]);
    h_out[r * OUTC + c] = hv;
    split_store(Gb, r, c, hv);
    split_store(Gb, r, OUTC + c,      x[r * HID + c]);
    split_store(Gb, r, OUTC + 64 + c, x[r * HID + 64 + c]);
    atomicAdd(&ssum[c], hv);
    atomicAdd(&ssq[c], hv * hv);
    __syncthreads();
    if (ty == 0) {
        atomicAdd(&stats[c], ssum[c]);
        atomicAdd(&stats[OUTC + c], ssq[c]);
    }
}

__global__ void bn_out(const float* __restrict__ h, const float* __restrict__ stats,
                       const float* __restrict__ gamma, const float* __restrict__ beta,
                       float* __restrict__ out)
{
    int i = blockIdx.x * blockDim.x + threadIdx.x;
    if (i >= NROWS * OUTC) return;
    int c = i & 63;
    float inv = 1.f / (float)NROWS;
    float mean = stats[c] * inv;
    float var  = stats[OUTC + c] * inv - mean * mean;
    out[i] = (h[i] - mean) * rsqrtf(var + 1e-5f) * gamma[c] + beta[c];
}

// ---------------------------------------------------------------------------
// HMMA SYRK with cp.async A-chunk pipeline.
// B tile fully resident (K=384, row stride 392 bf16 = 784B).
// A in 4 chunks of K=96 (row stride 104 bf16 = 208B), double-buffered.
// Chunk schedule (loads each A chunk exactly once):
//   A0 x {B[0:96], B[192:288]}, A1 x {B[96:192], B[288:384]},
//   A2 x {B[0:96]},             A3 x {B[96:192]}          = 36 k16 steps.
// ---------------------------------------------------------------------------
#define B_STRIDE     784
#define SMEM_B_BYTES (128 * B_STRIDE)          // 100352
#define A_STRIDE     208
#define A_CHUNK_B    (128 * A_STRIDE)          // 26624
#define SYRK_SMEM    (SMEM_B_BYTES + 2 * A_CHUNK_B)   // 153600

__device__ __forceinline__ void load_a_chunk(uint32_t dstBase,
                                             const __nv_bfloat16* __restrict__ GbA,
                                             int chunk, int tid) {
#pragma unroll 2
    for (int i = tid; i < 128 * 12; i += 256) {
        int row = i / 12, q = i % 12;
        cp16(dstBase + row * A_STRIDE + q * 16,
             GbA + (size_t)row * TK + chunk * 96 + q * 8);
    }
}

__global__ void __launch_bounds__(256, 1) big_syrk_mma(
    const __nv_bfloat16* __restrict__ Gb, float* __restrict__ C)
{
    extern __shared__ char smem[];
    const uint32_t smB  = smem_u32(smem);
    const uint32_t smA0 = smB + SMEM_B_BYTES;
    const uint32_t smA1 = smA0 + A_CHUNK_B;

    const int tid = threadIdx.x;
    const int wid = tid >> 5;
    const int lid = tid & 31;

    int idx = blockIdx.x;
    int bi = 0;
    while (bi < 63 && (64 * (bi + 1) - ((bi + 1) * bi) / 2) <= idx) bi++;
    int bj = bi + (idx - (64 * bi - (bi * (bi - 1)) / 2));

    const __nv_bfloat16* GbA = Gb + (size_t)(bi * 128) * TK;
    const __nv_bfloat16* GbB = Gb + (size_t)(bj * 128) * TK;

    // prologue: B full + A0 (group 1), A1 (group 2)
#pragma unroll 4
    for (int i = tid; i < 128 * 48; i += 256) {
        int row = i / 48, q = i % 48;
        cp16(smB + row * B_STRIDE + q * 16, GbB + (size_t)row * TK + q * 8);
    }
    load_a_chunk(smA0, GbA, 0, tid);
    cp_commit();
    load_a_chunk(smA1, GbA, 1, tid);
    cp_commit();

    const int wm = wid >> 2;
    const int wn = wid & 3;
    const int m_base = wm * 64;
    const int n0 = wn * 32;

    const int aRow = m_base + (lid & 15);
    const int aColH = (lid >> 4) * 8;
    const int bRow = n0 + ((lid >> 4) * 8) + (lid & 7);
    const int bColH = ((lid >> 3) & 1) * 8;

    float acc[4][4][4];
#pragma unroll
    for (int mf = 0; mf < 4; mf++)
#pragma unroll
        for (int nf = 0; nf < 4; nf++)
#pragma unroll
            for (int q = 0; q < 4; q++) acc[mf][nf][q] = 0.f;

    const int nbo[4] = {2, 2, 1, 1};
    const int boA[4] = {0, 96, 0, 96};      // first B k-offset for this A chunk
    const int boB[4] = {192, 288, 0, 0};    // second (when nbo==2)

#pragma unroll
    for (int c = 0; c < 4; c++) {
        if (c < 3) cp_wait<1>(); else cp_wait<0>();
        __syncthreads();
        const uint32_t smAc = (c & 1) ? smA1 : smA0;

#pragma unroll
        for (int pb = 0; pb < 2; pb++) {
            if (pb >= nbo[c]) break;
            const int bo = pb ? boB[c] : boA[c];
#pragma unroll
            for (int s = 0; s < 6; s++) {
                const int ka = s * 16;           // within chunk
                const int kb = bo + s * 16;      // within resident B
                uint32_t a[4][4];
#pragma unroll
                for (int mf = 0; mf < 4; mf++)
                    ldm_x4(a[mf], smAc + (uint32_t)((aRow + mf * 16) * A_STRIDE
                                                    + (ka + aColH) * 2));
                uint32_t b[4][2];
#pragma unroll
                for (int q = 0; q < 2; q++) {
                    uint32_t r[4];
                    ldm_x4(r, smB + (uint32_t)((bRow + q * 16) * B_STRIDE
                                               + (kb + bColH) * 2));
                    b[2 * q + 0][0] = r[0]; b[2 * q + 0][1] = r[1];
                    b[2 * q + 1][0] = r[2]; b[2 * q + 1][1] = r[3];
                }
#pragma unroll
                for (int mf = 0; mf < 4; mf++)
#pragma unroll
                    for (int nf = 0; nf < 4; nf++)
                        mma16816(acc[mf][nf], a[mf], b[nf]);
            }
        }
        __syncthreads();
        if (c + 2 < 4) {
            load_a_chunk((c & 1) ? smA1 : smA0, GbA, c + 2, tid);
            cp_commit();
        }
    }

    // ---- epilogue ----
    const int r0g = bi * 128, c0g = bj * 128;
    const int lrow = lid >> 2;
    const int lcol = (lid & 3) * 2;

#pragma unroll
    for (int mf = 0; mf < 4; mf++) {
#pragma unroll
        for (int nf = 0; nf < 4; nf++) {
            int row = m_base + mf * 16 + lrow;
            int col = n0 + nf * 8 + lcol;
            float2 v0 = make_float2(0.5f * acc[mf][nf][0], 0.5f * acc[mf][nf][1]);
            float2 v1 = make_float2(0.5f * acc[mf][nf][2], 0.5f * acc[mf][nf][3]);
            *(float2*)(C + (size_t)(r0g + row) * NROWS + c0g + col)     = v0;
            *(float2*)(C + (size_t)(r0g + row + 8) * NROWS + c0g + col) = v1;
        }
    }

    if (bi != bj) {
        __syncthreads();
        float* smT = (float*)smem;   // 128 x 132 transpose buffer (67.6KB)
#pragma unroll
        for (int mf = 0; mf < 4; mf++) {
#pragma unroll
            for (int nf = 0; nf < 4; nf++) {
                int row = m_base + mf * 16 + lrow;
                int col = n0 + nf * 8 + lcol;
                smT[(col + 0) * 132 + row]     = 0.5f * acc[mf][nf][0];
                smT[(col + 1) * 132 + row]     = 0.5f * acc[mf][nf][1];
                smT[(col + 0) * 132 + row + 8] = 0.5f * acc[mf][nf][2];
                smT[(col + 1) * 132 + row + 8] = 0.5f * acc[mf][nf][3];
            }
        }
        __syncthreads();
        for (int i = tid; i < 128 * 32; i += 256) {
            int c = i >> 5, q = i & 31;
            float4 v = *(float4*)&smT[c * 132 + q * 4];
            *(float4*)(C + (size_t)(c0g + c) * NROWS + r0g + q * 4) = v;
        }
    }
}

// ---------------------------------------------------------------------------
// Launch
// Inputs: 0:x 1:adj 2:src 3:dst 4:fc_w 5:fc_b 6:w1 7:w1_b 8:w2 9:w2_b
//         10:epsilon 11:gamma 12:beta
// ---------------------------------------------------------------------------
extern "C" void kernel_launch(void* const* d_in, const int* in_sizes, int n_in,
                              void* d_out, int out_size)
{
    const float* x     = (const float*)d_in[0];
    const int*   src   = (const int*)d_in[2];
    const int*   dst   = (const int*)d_in[3];
    const float* fc_w  = (const float*)d_in[4];
    const float* fc_b  = (const float*)d_in[5];
    const float* w1    = (const float*)d_in[6];
    const float* w1_b  = (const float*)d_in[7];
    const float* w2    = (const float*)d_in[8];
    const float* w2_b  = (const float*)d_in[9];
    const float* epsv  = (const float*)d_in[10];
    const float* gamma = (const float*)d_in[11];
    const float* beta  = (const float*)d_in[12];
    const int E = in_sizes[2];

    float* out_ret = (float*)d_out;
    float* out_bn  = (float*)d_out + (size_t)RET_ELEMS;

    float *y1, *z1, *h1, *y2, *z2, *h, *stats;
    __nv_bfloat16* Gb;
    cudaGetSymbolAddress((void**)&y1, g_y1);
    cudaGetSymbolAddress((void**)&z1, g_z1);
    cudaGetSymbolAddress((void**)&h1, g_h1);
    cudaGetSymbolAddress((void**)&y2, g_y2);
    cudaGetSymbolAddress((void**)&z2, g_z2);
    cudaGetSymbolAddress((void**)&h,  g_h);
    cudaGetSymbolAddress((void**)&Gb, g_Gb);
    cudaGetSymbolAddress((void**)&stats, g_stats);

    cudaFuncSetAttribute(big_syrk_mma, cudaFuncAttributeMaxDynamicSharedMemorySize,
                         SYRK_SMEM);

    // CSR build
    zero_small<<<(NROWS + 255) / 256, 256>>>();
    hist_kernel<<<512, 256>>>(dst, E);
    scan_kernel<<<1, 1024>>>();
    scatter_kernel<<<512, 256>>>(src, dst, E);

    // y1 = x @ w1 ; h1 = x @ fc_w + fc_b
    small_gemm<<<dim3(NROWS / 64, HID / 64), 256>>>(x, nullptr, w1, nullptr,
                                                    y1, NROWS, HID, 0);
    small_gemm<<<dim3(NROWS / 64, OUTC / 64), 256>>>(x, nullptr, fc_w, fc_b,
                                                     h1, NROWS, OUTC, 0);

    // z1 = segsum(y1)
    gather_kernel<32><<<NROWS * 32 / 256, 256>>>(y1, z1);

    // y2 = relu(z1 + w1_b) @ w2
    small_gemm<<<dim3(NROWS / 64, OUTC / 64), 256>>>(z1, w1_b, w2, nullptr,
                                                     y2, NROWS, OUTC, 1);
    // z2 = segsum(y2)
    gather_kernel<16><<<NROWS * 16 / 256, 256>>>(y2, z2);

    build_h<<<NROWS / 8, dim3(64, 8)>>>(h1, z2, w2_b, x, epsv, h, Gb, stats);
    bn_out<<<(NROWS * OUTC + 255) / 256, 256>>>(h, stats, gamma, beta, out_bn);

    big_syrk_mma<<<(64 * 65) / 2, 256, SYRK_SMEM>>>(Gb, out_ret);
}

// round 7
// speedup vs baseline: 2.3638x; 1.1279x over previous
#include <cuda_runtime.h>
#include <cuda_bf16.h>
#include <cstdint>
#include <math.h>

#define NROWS 8192
#define HID   128
#define OUTC  64
#define GDIM  192          // [h(64) | x(128)]
#define TK    384          // [hi(192) | lo(192)] bf16
#define EMAX  262144
#define RET_ELEMS (NROWS * NROWS)

// ---------------------------------------------------------------------------
// Scratch (device globals)
// ---------------------------------------------------------------------------
__device__ float g_y1[NROWS * HID];
__device__ float g_z1[NROWS * HID];
__device__ float g_h1[NROWS * OUTC];
__device__ float g_y2[NROWS * OUTC];
__device__ float g_z2[NROWS * OUTC];
__device__ float g_h [NROWS * OUTC];          // fp32 h for BN
__device__ __nv_bfloat16 g_Gb[NROWS * TK];    // [Gh | Gl] bf16 split
__device__ float g_stats[2 * OUTC];
// CSR scratch
__device__ int g_deg[NROWS];
__device__ int g_off[NROWS + 1];
__device__ int g_cur[NROWS];
__device__ int g_csr[EMAX];

// ---------------------------------------------------------------------------
// helpers
// ---------------------------------------------------------------------------
__device__ __forceinline__ uint32_t smem_u32(const void* p) {
    uint32_t a;
    asm("{ .reg .u64 t; cvta.to.shared.u64 t, %1; cvt.u32.u64 %0, t; }" : "=r"(a) : "l"(p));
    return a;
}
__device__ __forceinline__ void ldm_x4(uint32_t* r, uint32_t addr) {
    asm volatile("ldmatrix.sync.aligned.m8n8.x4.shared.b16 {%0,%1,%2,%3}, [%4];"
                 : "=r"(r[0]), "=r"(r[1]), "=r"(r[2]), "=r"(r[3]) : "r"(addr));
}
__device__ __forceinline__ void mma16816(float* d, const uint32_t* a, const uint32_t* b) {
    asm volatile("mma.sync.aligned.m16n8k16.row.col.f32.bf16.bf16.f32 "
                 "{%0,%1,%2,%3}, {%4,%5,%6,%7}, {%8,%9}, {%0,%1,%2,%3};"
                 : "+f"(d[0]), "+f"(d[1]), "+f"(d[2]), "+f"(d[3])
                 : "r"(a[0]), "r"(a[1]), "r"(a[2]), "r"(a[3]), "r"(b[0]), "r"(b[1]));
}
__device__ __forceinline__ void cp16(uint32_t smem_dst, const void* gsrc) {
    asm volatile("cp.async.cg.shared.global [%0], [%1], 16;"
                 :: "r"(smem_dst), "l"(gsrc) : "memory");
}
__device__ __forceinline__ void cp_commit() {
    asm volatile("cp.async.commit_group;" ::: "memory");
}
template <int N>
__device__ __forceinline__ void cp_wait() {
    asm volatile("cp.async.wait_group %0;" :: "n"(N) : "memory");
}

// ---------------------------------------------------------------------------
// CSR build: zero -> histogram -> scan -> scatter
// ---------------------------------------------------------------------------
__global__ void zero_small() {
    int i = blockIdx.x * blockDim.x + threadIdx.x;
    if (i < NROWS) g_deg[i] = 0;
    if (i < 2 * OUTC) g_stats[i] = 0.f;
}

__global__ void hist_kernel(const int* __restrict__ dst, int E) {
    int i = blockIdx.x * blockDim.x + threadIdx.x;
    int stride = gridDim.x * blockDim.x;
    for (int e = i; e < E; e += stride) atomicAdd(&g_deg[dst[e]], 1);
}

__global__ void __launch_bounds__(1024) scan_kernel() {
    __shared__ int ssum[1024];
    int t = threadIdx.x;
    int v[8];
    int tot = 0;
#pragma unroll
    for (int j = 0; j < 8; j++) { v[j] = g_deg[t * 8 + j]; tot += v[j]; }
    ssum[t] = tot;
    __syncthreads();
    for (int d = 1; d < 1024; d <<= 1) {
        int x = (t >= d) ? ssum[t - d] : 0;
        __syncthreads();
        ssum[t] += x;
        __syncthreads();
    }
    int run = ssum[t] - tot;   // exclusive prefix
#pragma unroll
    for (int j = 0; j < 8; j++) {
        g_off[t * 8 + j] = run;
        g_cur[t * 8 + j] = run;
        run += v[j];
    }
    if (t == 1023) g_off[NROWS] = run;
}

__global__ void scatter_kernel(const int* __restrict__ src,
                               const int* __restrict__ dst, int E) {
    int i = blockIdx.x * blockDim.x + threadIdx.x;
    int stride = gridDim.x * blockDim.x;
    for (int e = i; e < E; e += stride) {
        int p = atomicAdd(&g_cur[dst[e]], 1);
        g_csr[p] = src[e];
    }
}

// ---------------------------------------------------------------------------
// CSR gather segment-sum
// ---------------------------------------------------------------------------
template <int TPD>
__global__ void __launch_bounds__(256) gather_kernel(
    const float* __restrict__ feat, float* __restrict__ out)
{
    const int F = TPD * 4;
    int g = (blockIdx.x * blockDim.x + threadIdx.x) / TPD;
    int lane = threadIdx.x % TPD;
    if (g >= NROWS) return;
    int b = g_off[g];
    int e = g_off[g + 1];
    float4 acc = make_float4(0.f, 0.f, 0.f, 0.f);
    float4 acc2 = make_float4(0.f, 0.f, 0.f, 0.f);
    int i = b;
    for (; i + 1 < e; i += 2) {
        int s0 = g_csr[i];
        int s1 = g_csr[i + 1];
        float4 v0 = *(const float4*)(feat + (size_t)s0 * F + lane * 4);
        float4 v1 = *(const float4*)(feat + (size_t)s1 * F + lane * 4);
        acc.x += v0.x; acc.y += v0.y; acc.z += v0.z; acc.w += v0.w;
        acc2.x += v1.x; acc2.y += v1.y; acc2.z += v1.z; acc2.w += v1.w;
    }
    if (i < e) {
        int s0 = g_csr[i];
        float4 v0 = *(const float4*)(feat + (size_t)s0 * F + lane * 4);
        acc.x += v0.x; acc.y += v0.y; acc.z += v0.z; acc.w += v0.w;
    }
    acc.x += acc2.x; acc.y += acc2.y; acc.z += acc2.z; acc.w += acc2.w;
    *(float4*)(out + (size_t)g * F + lane * 4) = acc;
}

// ---------------------------------------------------------------------------
// Small GEMM (unchanged, known-good)
// ---------------------------------------------------------------------------
__global__ void __launch_bounds__(256) small_gemm(
    const float* __restrict__ A, const float* __restrict__ abias,
    const float* __restrict__ B, const float* __restrict__ cbias,
    float* __restrict__ C, int M, int Nc, int relu)
{
    __shared__ float As[16][64];
    __shared__ float Bs[16][64];
    const int row0 = blockIdx.x * 64;
    const int col0 = blockIdx.y * 64;
    const int tid = threadIdx.x;
    const int tx = tid & 15, ty = tid >> 4;

    float acc[4][4];
#pragma unroll
    for (int i = 0; i < 4; i++)
#pragma unroll
        for (int j = 0; j < 4; j++) acc[i][j] = 0.f;

    for (int k0 = 0; k0 < HID; k0 += 16) {
        {
            int r = tid >> 2;
            int c4 = (tid & 3) * 4;
            float4 v = *(const float4*)(A + (size_t)(row0 + r) * HID + k0 + c4);
            if (relu) {
                v.x = fmaxf(v.x + abias[k0 + c4 + 0], 0.f);
                v.y = fmaxf(v.y + abias[k0 + c4 + 1], 0.f);
                v.z = fmaxf(v.z + abias[k0 + c4 + 2], 0.f);
                v.w = fmaxf(v.w + abias[k0 + c4 + 3], 0.f);
            }
            As[c4 + 0][r] = v.x; As[c4 + 1][r] = v.y;
            As[c4 + 2][r] = v.z; As[c4 + 3][r] = v.w;
        }
        {
            int kr = tid >> 4;
            int c = (tid & 15) * 4;
            float4 v = *(const float4*)(B + (size_t)(k0 + kr) * Nc + col0 + c);
            *(float4*)&Bs[kr][c] = v;
        }
        __syncthreads();
#pragma unroll
        for (int kk = 0; kk < 16; kk++) {
            float av[4], bv[4];
#pragma unroll
            for (int i = 0; i < 4; i++) av[i] = As[kk][ty * 4 + i];
#pragma unroll
            for (int j = 0; j < 4; j++) bv[j] = Bs[kk][tx * 4 + j];
#pragma unroll
            for (int i = 0; i < 4; i++)
#pragma unroll
                for (int j = 0; j < 4; j++) acc[i][j] += av[i] * bv[j];
        }
        __syncthreads();
    }
#pragma unroll
    for (int i = 0; i < 4; i++)
#pragma unroll
        for (int j = 0; j < 4; j++) {
            int c = col0 + tx * 4 + j;
            float cb = cbias ? cbias[c] : 0.f;
            C[(size_t)(row0 + ty * 4 + i) * Nc + c] = acc[i][j] + cb;
        }
}

// ---------------------------------------------------------------------------
// Build h, bf16 hi/lo split of G=[h|x] into g_Gb, BN stats.
// ---------------------------------------------------------------------------
__device__ __forceinline__ void split_store(__nv_bfloat16* Gb, size_t r, int col, float v) {
    __nv_bfloat16 hi = __float2bfloat16(v);
    __nv_bfloat16 lo = __float2bfloat16(v - __bfloat162float(hi));
    Gb[r * TK + col]        = hi;
    Gb[r * TK + GDIM + col] = lo;
}

__global__ void build_h(const float* __restrict__ h1, const float* __restrict__ z2,
                        const float* __restrict__ w2b, const float* __restrict__ x,
                        const float* __restrict__ epsv,
                        float* __restrict__ h_out, __nv_bfloat16* __restrict__ Gb,
                        float* __restrict__ stats)
{
    __shared__ float ssum[OUTC];
    __shared__ float ssq[OUTC];
    int c = threadIdx.x;
    int ty = threadIdx.y;
    if (ty == 0) { ssum[c] = 0.f; ssq[c] = 0.f; }
    __syncthreads();

    size_t r = blockIdx.x * 8 + ty;
    float e  = epsv[r];
    float hv = (1.f - e) * h1[r * OUTC + c] + e * (z2[r * OUTC + c] + w2b[c]);
    h_out[r * OUTC + c] = hv;
    split_store(Gb, r, c, hv);
    split_store(Gb, r, OUTC + c,      x[r * HID + c]);
    split_store(Gb, r, OUTC + 64 + c, x[r * HID + 64 + c]);
    atomicAdd(&ssum[c], hv);
    atomicAdd(&ssq[c], hv * hv);
    __syncthreads();
    if (ty == 0) {
        atomicAdd(&stats[c], ssum[c]);
        atomicAdd(&stats[OUTC + c], ssq[c]);
    }
}

__global__ void bn_out(const float* __restrict__ h, const float* __restrict__ stats,
                       const float* __restrict__ gamma, const float* __restrict__ beta,
                       float* __restrict__ out)
{
    int i = blockIdx.x * blockDim.x + threadIdx.x;
    if (i >= NROWS * OUTC) return;
    int c = i & 63;
    float inv = 1.f / (float)NROWS;
    float mean = stats[c] * inv;
    float var  = stats[OUTC + c] * inv - mean * mean;
    out[i] = (h[i] - mean) * rsqrtf(var + 1e-5f) * gamma[c] + beta[c];
}

// ---------------------------------------------------------------------------
// HMMA SYRK, single contiguous pass over K=384 ([Gh|Gl] concat):
//   Gb Gb^T = (Gh+Gl)(Gh+Gl)^T ~= G G^T  (error ~2^-17 relative)
// 24 k16-steps (was 36 in the 3-pass version). B tile fully resident;
// A double-buffered in 4 chunks of K=96, chunk c pairs with B[96c:96c+96].
// ---------------------------------------------------------------------------
#define B_STRIDE     784
#define SMEM_B_BYTES (128 * B_STRIDE)          // 100352
#define A_STRIDE     208
#define A_CHUNK_B    (128 * A_STRIDE)          // 26624
#define SYRK_SMEM    (SMEM_B_BYTES + 2 * A_CHUNK_B)   // 153600

__device__ __forceinline__ void load_a_chunk(uint32_t dstBase,
                                             const __nv_bfloat16* __restrict__ GbA,
                                             int chunk, int tid) {
#pragma unroll 2
    for (int i = tid; i < 128 * 12; i += 256) {
        int row = i / 12, q = i % 12;
        cp16(dstBase + row * A_STRIDE + q * 16,
             GbA + (size_t)row * TK + chunk * 96 + q * 8);
    }
}

__global__ void __launch_bounds__(256, 1) big_syrk_mma(
    const __nv_bfloat16* __restrict__ Gb, float* __restrict__ C)
{
    extern __shared__ char smem[];
    const uint32_t smB  = smem_u32(smem);
    const uint32_t smA0 = smB + SMEM_B_BYTES;
    const uint32_t smA1 = smA0 + A_CHUNK_B;

    const int tid = threadIdx.x;
    const int wid = tid >> 5;
    const int lid = tid & 31;

    int idx = blockIdx.x;
    int bi = 0;
    while (bi < 63 && (64 * (bi + 1) - ((bi + 1) * bi) / 2) <= idx) bi++;
    int bj = bi + (idx - (64 * bi - (bi * (bi - 1)) / 2));

    const __nv_bfloat16* GbA = Gb + (size_t)(bi * 128) * TK;
    const __nv_bfloat16* GbB = Gb + (size_t)(bj * 128) * TK;

    // prologue: B full + A0 (group 1), A1 (group 2)
#pragma unroll 4
    for (int i = tid; i < 128 * 48; i += 256) {
        int row = i / 48, q = i % 48;
        cp16(smB + row * B_STRIDE + q * 16, GbB + (size_t)row * TK + q * 8);
    }
    load_a_chunk(smA0, GbA, 0, tid);
    cp_commit();
    load_a_chunk(smA1, GbA, 1, tid);
    cp_commit();

    const int wm = wid >> 2;
    const int wn = wid & 3;
    const int m_base = wm * 64;
    const int n0 = wn * 32;

    const int aRow = m_base + (lid & 15);
    const int aColH = (lid >> 4) * 8;
    const int bRow = n0 + ((lid >> 4) * 8) + (lid & 7);
    const int bColH = ((lid >> 3) & 1) * 8;

    float acc[4][4][4];
#pragma unroll
    for (int mf = 0; mf < 4; mf++)
#pragma unroll
        for (int nf = 0; nf < 4; nf++)
#pragma unroll
            for (int q = 0; q < 4; q++) acc[mf][nf][q] = 0.f;

#pragma unroll
    for (int c = 0; c < 4; c++) {
        if (c < 3) cp_wait<1>(); else cp_wait<0>();
        __syncthreads();
        const uint32_t smAc = (c & 1) ? smA1 : smA0;
        const int bo = c * 96;                    // B k-offset for this chunk

#pragma unroll
        for (int s = 0; s < 6; s++) {
            const int ka = s * 16;                // within A chunk
            const int kb = bo + s * 16;           // within resident B
            uint32_t a[4][4];
#pragma unroll
            for (int mf = 0; mf < 4; mf++)
                ldm_x4(a[mf], smAc + (uint32_t)((aRow + mf * 16) * A_STRIDE
                                                + (ka + aColH) * 2));
            uint32_t b[4][2];
#pragma unroll
            for (int q = 0; q < 2; q++) {
                uint32_t r[4];
                ldm_x4(r, smB + (uint32_t)((bRow + q * 16) * B_STRIDE
                                           + (kb + bColH) * 2));
                b[2 * q + 0][0] = r[0]; b[2 * q + 0][1] = r[1];
                b[2 * q + 1][0] = r[2]; b[2 * q + 1][1] = r[3];
            }
#pragma unroll
            for (int mf = 0; mf < 4; mf++)
#pragma unroll
                for (int nf = 0; nf < 4; nf++)
                    mma16816(acc[mf][nf], a[mf], b[nf]);
        }
        __syncthreads();
        if (c + 2 < 4) {
            load_a_chunk((c & 1) ? smA1 : smA0, GbA, c + 2, tid);
            cp_commit();
        }
    }

    // ---- epilogue ----
    const int r0g = bi * 128, c0g = bj * 128;
    const int lrow = lid >> 2;
    const int lcol = (lid & 3) * 2;

#pragma unroll
    for (int mf = 0; mf < 4; mf++) {
#pragma unroll
        for (int nf = 0; nf < 4; nf++) {
            int row = m_base + mf * 16 + lrow;
            int col = n0 + nf * 8 + lcol;
            float2 v0 = make_float2(0.5f * acc[mf][nf][0], 0.5f * acc[mf][nf][1]);
            float2 v1 = make_float2(0.5f * acc[mf][nf][2], 0.5f * acc[mf][nf][3]);
            *(float2*)(C + (size_t)(r0g + row) * NROWS + c0g + col)     = v0;
            *(float2*)(C + (size_t)(r0g + row + 8) * NROWS + c0g + col) = v1;
        }
    }

    if (bi != bj) {
        __syncthreads();
        float* smT = (float*)smem;   // 128 x 132 transpose buffer (67.6KB)
#pragma unroll
        for (int mf = 0; mf < 4; mf++) {
#pragma unroll
            for (int nf = 0; nf < 4; nf++) {
                int row = m_base + mf * 16 + lrow;
                int col = n0 + nf * 8 + lcol;
                smT[(col + 0) * 132 + row]     = 0.5f * acc[mf][nf][0];
                smT[(col + 1) * 132 + row]     = 0.5f * acc[mf][nf][1];
                smT[(col + 0) * 132 + row + 8] = 0.5f * acc[mf][nf][2];
                smT[(col + 1) * 132 + row + 8] = 0.5f * acc[mf][nf][3];
            }
        }
        __syncthreads();
        for (int i = tid; i < 128 * 32; i += 256) {
            int c = i >> 5, q = i & 31;
            float4 v = *(float4*)&smT[c * 132 + q * 4];
            *(float4*)(C + (size_t)(c0g + c) * NROWS + r0g + q * 4) = v;
        }
    }
}

// ---------------------------------------------------------------------------
// Launch
// Inputs: 0:x 1:adj 2:src 3:dst 4:fc_w 5:fc_b 6:w1 7:w1_b 8:w2 9:w2_b
//         10:epsilon 11:gamma 12:beta
// ---------------------------------------------------------------------------
extern "C" void kernel_launch(void* const* d_in, const int* in_sizes, int n_in,
                              void* d_out, int out_size)
{
    const float* x     = (const float*)d_in[0];
    const int*   src   = (const int*)d_in[2];
    const int*   dst   = (const int*)d_in[3];
    const float* fc_w  = (const float*)d_in[4];
    const float* fc_b  = (const float*)d_in[5];
    const float* w1    = (const float*)d_in[6];
    const float* w1_b  = (const float*)d_in[7];
    const float* w2    = (const float*)d_in[8];
    const float* w2_b  = (const float*)d_in[9];
    const float* epsv  = (const float*)d_in[10];
    const float* gamma = (const float*)d_in[11];
    const float* beta  = (const float*)d_in[12];
    const int E = in_sizes[2];

    float* out_ret = (float*)d_out;
    float* out_bn  = (float*)d_out + (size_t)RET_ELEMS;

    float *y1, *z1, *h1, *y2, *z2, *h, *stats;
    __nv_bfloat16* Gb;
    cudaGetSymbolAddress((void**)&y1, g_y1);
    cudaGetSymbolAddress((void**)&z1, g_z1);
    cudaGetSymbolAddress((void**)&h1, g_h1);
    cudaGetSymbolAddress((void**)&y2, g_y2);
    cudaGetSymbolAddress((void**)&z2, g_z2);
    cudaGetSymbolAddress((void**)&h,  g_h);
    cudaGetSymbolAddress((void**)&Gb, g_Gb);
    cudaGetSymbolAddress((void**)&stats, g_stats);

    cudaFuncSetAttribute(big_syrk_mma, cudaFuncAttributeMaxDynamicSharedMemorySize,
                         SYRK_SMEM);

    // CSR build
    zero_small<<<(NROWS + 255) / 256, 256>>>();
    hist_kernel<<<512, 256>>>(dst, E);
    scan_kernel<<<1, 1024>>>();
    scatter_kernel<<<512, 256>>>(src, dst, E);

    // y1 = x @ w1 ; h1 = x @ fc_w + fc_b
    small_gemm<<<dim3(NROWS / 64, HID / 64), 256>>>(x, nullptr, w1, nullptr,
                                                    y1, NROWS, HID, 0);
    small_gemm<<<dim3(NROWS / 64, OUTC / 64), 256>>>(x, nullptr, fc_w, fc_b,
                                                     h1, NROWS, OUTC, 0);

    // z1 = segsum(y1)
    gather_kernel<32><<<NROWS * 32 / 256, 256>>>(y1, z1);

    // y2 = relu(z1 + w1_b) @ w2
    small_gemm<<<dim3(NROWS / 64, OUTC / 64), 256>>>(z1, w1_b, w2, nullptr,
                                                     y2, NROWS, OUTC, 1);
    // z2 = segsum(y2)
    gather_kernel<16><<<NROWS * 16 / 256, 256>>>(y2, z2);

    build_h<<<NROWS / 8, dim3(64, 8)>>>(h1, z2, w2_b, x, epsv, h, Gb, stats);
    bn_out<<<(NROWS * OUTC + 255) / 256, 256>>>(h, stats, gamma, beta, out_bn);

    big_syrk_mma<<<(64 * 65) / 2, 256, SYRK_SMEM>>>(Gb, out_ret);
}